// round 2
// baseline (speedup 1.0000x reference)
#include <cuda_runtime.h>
#include <math.h>

#define N_    8192
#define K_    200
#define CIN_  512
#define HID_  256
#define COUT_ 40
#define E_    5
#define MH_   64
#define KG_   40
#define TLUT  8192
#define NS_   16
#define EPS_  1e-5f

// ---------------- device scratch (no allocation allowed) ----------------
__device__ __align__(16) float d_g[E_];
__device__ __align__(16) float d_lut[E_*TLUT];
__device__ __align__(16) float d_s[K_];
__device__ __align__(16) float d_Mpart[(size_t)NS_*K_*CIN_];   // split-N partials of U^T X
__device__ __align__(16) float d_P[K_*HID_];                   // s * (U^T X) Ww
__device__ __align__(16) float d_bnsum[64*HID_];
__device__ __align__(16) float d_bnsq[64*HID_];
__device__ __align__(16) float d_scale[HID_];
__device__ __align__(16) float d_shift[HID_];

// ---------------- gate: softmax(relu(stats@gW1+gb1)@gW2+gb2) ----------------
__global__ void gate_kernel(const float* __restrict__ La, const float* __restrict__ gW1,
                            const float* __restrict__ gb1, const float* __restrict__ gW2,
                            const float* __restrict__ gb2){
    if (threadIdx.x != 0) return;
    float stats[E_];
    for (int e = 0; e < E_; e++){
        float s = 0.f;
        for (int i = 0; i < KG_; i++) s += La[e*KG_ + i];
        stats[e] = s / (float)KG_;
    }
    float t1[E_];
    for (int j = 0; j < E_; j++){
        float z = gb1[j];
        for (int i = 0; i < E_; i++) z += stats[i]*gW1[i*E_+j];
        t1[j] = fmaxf(z, 0.f);
    }
    float t2[E_]; float mx = -1e30f;
    for (int j = 0; j < E_; j++){
        float z = gb2[j];
        for (int i = 0; i < E_; i++) z += t1[i]*gW2[i*E_+j];
        t2[j] = z; mx = fmaxf(mx, z);
    }
    float den = 0.f;
    for (int j = 0; j < E_; j++){ t2[j] = expf(t2[j]-mx); den += t2[j]; }
    for (int j = 0; j < E_; j++) d_g[j] = t2[j]/den;
}

// ---------------- LUT build: f_e(u) sampled on [-8,8], TLUT points ----------------
__global__ __launch_bounds__(128) void lut_kernel(
        const float* __restrict__ eW1, const float* __restrict__ eb1,
        const float* __restrict__ eW2, const float* __restrict__ eb2,
        const float* __restrict__ eW3, const float* __restrict__ eb3){
    int e = blockIdx.y;
    __shared__ __align__(16) float w2t[MH_*MH_];   // [g][h]
    __shared__ float w1[MH_], b1[MH_], b2s[MH_], w3[MH_];
    for (int i = threadIdx.x; i < MH_*MH_; i += blockDim.x){
        int h = i >> 6, g = i & 63;
        w2t[g*MH_ + h] = eW2[(e*MH_ + h)*MH_ + g];
    }
    if (threadIdx.x < MH_){
        int t = threadIdx.x;
        w1[t]  = eW1[e*MH_+t];
        b1[t]  = eb1[e*MH_+t];
        b2s[t] = eb2[e*MH_+t];
        w3[t]  = eW3[e*MH_+t];
    }
    __syncthreads();
    int j = blockIdx.x*blockDim.x + threadIdx.x;
    float u = -8.f + 16.f*(float)j/(float)(TLUT-1);
    float h1[MH_];
    #pragma unroll
    for (int h = 0; h < MH_; h++) h1[h] = fmaxf(fmaf(u, w1[h], b1[h]), 0.f);
    float acc = eb3[e];
    #pragma unroll 2
    for (int g = 0; g < MH_; g++){
        float z = b2s[g];
        const float4* row = (const float4*)(w2t + g*MH_);
        #pragma unroll
        for (int q = 0; q < 16; q++){
            float4 w = row[q];
            z = fmaf(h1[4*q+0], w.x, z);
            z = fmaf(h1[4*q+1], w.y, z);
            z = fmaf(h1[4*q+2], w.z, z);
            z = fmaf(h1[4*q+3], w.w, z);
        }
        acc = fmaf(fmaxf(z, 0.f), w3[g], acc);
    }
    d_lut[e*TLUT + j] = acc;
}

// ---------------- s[col] = g[e] * mean_n f_e(U[n,col]) via LUT ----------------
__global__ __launch_bounds__(256) void vs_kernel(const float* __restrict__ U){
    int col = blockIdx.x;
    int e = col / KG_;
    const float* lut = d_lut + e*TLUT;
    const float invd = (float)(TLUT-1)/16.f;
    float sum = 0.f;
    for (int n = threadIdx.x; n < N_; n += blockDim.x){
        float u = U[(size_t)n*K_ + col];
        float t = (u + 8.f)*invd;
        int i = (int)floorf(t);
        i = min(max(i, 0), TLUT-2);
        float fr = t - (float)i;             // may extrapolate; exact in linear tails
        float a = lut[i];
        float b = lut[i+1];
        sum += a + (b - a)*fr;
    }
    __shared__ float red[256];
    red[threadIdx.x] = sum;
    __syncthreads();
    for (int off = 128; off > 0; off >>= 1){
        if (threadIdx.x < off) red[threadIdx.x] += red[threadIdx.x + off];
        __syncthreads();
    }
    if (threadIdx.x == 0) d_s[col] = d_g[e] * (red[0] / (float)N_);
}

// ---------------- Mpart[ns] = U[ns]^T @ X[ns]  (split-N) ----------------
__global__ __launch_bounds__(256) void gemmD(const float* __restrict__ U, const float* __restrict__ X){
    int c0 = blockIdx.x * 128;
    int k0 = blockIdx.y * 40;
    int n0 = blockIdx.z * (N_/NS_);
    __shared__ __align__(16) float Ush[32*40];
    __shared__ __align__(16) float Xsh[32*128];
    int tid = threadIdx.x;
    int kgrp = tid >> 5;     // 0..7 -> 5 k each
    int cq   = tid & 31;     // float4 group of c
    float acc[5][4];
    #pragma unroll
    for (int i = 0; i < 5; i++){ acc[i][0]=0.f; acc[i][1]=0.f; acc[i][2]=0.f; acc[i][3]=0.f; }

    for (int nc = 0; nc < N_/NS_; nc += 32){
        for (int i = tid; i < 320; i += 256){
            int nn = i/10, q = i - nn*10;
            *(float4*)(Ush + nn*40 + 4*q) =
                *(const float4*)(U + (size_t)(n0+nc+nn)*K_ + k0 + 4*q);
        }
        for (int i = tid; i < 1024; i += 256){
            int nn = i >> 5, q = i & 31;
            *(float4*)(Xsh + nn*128 + 4*q) =
                *(const float4*)(X + (size_t)(n0+nc+nn)*CIN_ + c0 + 4*q);
        }
        __syncthreads();
        #pragma unroll 4
        for (int nn = 0; nn < 32; nn++){
            float4 xv = *(const float4*)(Xsh + nn*128 + 4*cq);
            #pragma unroll
            for (int i = 0; i < 5; i++){
                float uv = Ush[nn*40 + kgrp*5 + i];
                acc[i][0] = fmaf(uv, xv.x, acc[i][0]);
                acc[i][1] = fmaf(uv, xv.y, acc[i][1]);
                acc[i][2] = fmaf(uv, xv.z, acc[i][2]);
                acc[i][3] = fmaf(uv, xv.w, acc[i][3]);
            }
        }
        __syncthreads();
    }
    float* outp = d_Mpart + (size_t)blockIdx.z*K_*CIN_;
    #pragma unroll
    for (int i = 0; i < 5; i++){
        float4 v = make_float4(acc[i][0], acc[i][1], acc[i][2], acc[i][3]);
        *(float4*)(outp + (size_t)(k0 + kgrp*5 + i)*CIN_ + c0 + 4*cq) = v;
    }
}

// ---------------- P[k,:] = s[k] * (sum_ns Mpart)[k,:] @ Ww ----------------
__global__ __launch_bounds__(256) void reduceP_kernel(const float* __restrict__ Ww){
    int k = blockIdx.x;
    __shared__ float m[CIN_];
    for (int c = threadIdx.x; c < CIN_; c += 256){
        float s = 0.f;
        for (int b = 0; b < NS_; b++) s += d_Mpart[(size_t)b*K_*CIN_ + (size_t)k*CIN_ + c];
        m[c] = s;
    }
    __syncthreads();
    int j = threadIdx.x;
    float a0=0.f, a1=0.f, a2=0.f, a3=0.f;
    for (int c = 0; c < CIN_; c += 4){
        a0 = fmaf(m[c+0], Ww[(c+0)*HID_+j], a0);
        a1 = fmaf(m[c+1], Ww[(c+1)*HID_+j], a1);
        a2 = fmaf(m[c+2], Ww[(c+2)*HID_+j], a2);
        a3 = fmaf(m[c+3], Ww[(c+3)*HID_+j], a3);
    }
    d_P[k*HID_ + j] = ((a0+a1)+(a2+a3)) * d_s[k];
}

// ---------------- hidden = U @ P + Wb ----------------
__global__ __launch_bounds__(256) void gemmE(const float* __restrict__ U, const float* __restrict__ Wb,
                                             float* __restrict__ hid_out){
    int c0 = blockIdx.x * 128;
    int r0 = blockIdx.y * 64;
    __shared__ __align__(16) float Ash[64*40];
    __shared__ __align__(16) float Psh[40*128];
    int tid = threadIdx.x;
    int rgrp = tid >> 5;     // 8 groups x 8 rows
    int cq   = tid & 31;
    float acc[8][4];
    #pragma unroll
    for (int i = 0; i < 8; i++){ acc[i][0]=0.f; acc[i][1]=0.f; acc[i][2]=0.f; acc[i][3]=0.f; }

    for (int kt = 0; kt < 5; kt++){
        int k0 = kt*40;
        for (int i = tid; i < 640; i += 256){
            int r = i/10, q = i - r*10;
            *(float4*)(Ash + r*40 + 4*q) =
                *(const float4*)(U + (size_t)(r0+r)*K_ + k0 + 4*q);
        }
        for (int i = tid; i < 1280; i += 256){
            int kk = i >> 5, q = i & 31;
            *(float4*)(Psh + kk*128 + 4*q) =
                *(const float4*)(d_P + (size_t)(k0+kk)*HID_ + c0 + 4*q);
        }
        __syncthreads();
        #pragma unroll 2
        for (int kk = 0; kk < 40; kk++){
            float4 b = *(const float4*)(Psh + kk*128 + 4*cq);
            #pragma unroll
            for (int i = 0; i < 8; i++){
                float a = Ash[(rgrp*8+i)*40 + kk];
                acc[i][0] = fmaf(a, b.x, acc[i][0]);
                acc[i][1] = fmaf(a, b.y, acc[i][1]);
                acc[i][2] = fmaf(a, b.z, acc[i][2]);
                acc[i][3] = fmaf(a, b.w, acc[i][3]);
            }
        }
        __syncthreads();
    }
    float4 wb = *(const float4*)(Wb + c0 + 4*cq);
    #pragma unroll
    for (int i = 0; i < 8; i++){
        float4 v = make_float4(acc[i][0]+wb.x, acc[i][1]+wb.y, acc[i][2]+wb.z, acc[i][3]+wb.w);
        *(float4*)(hid_out + (size_t)(r0+rgrp*8+i)*HID_ + c0 + 4*cq) = v;
    }
}

// ---------------- BN stats ----------------
__global__ __launch_bounds__(256) void bn_partial(const float* __restrict__ hid){
    int j = threadIdx.x;
    int s = blockIdx.x;               // 64 blocks x 128 rows
    float sum = 0.f, sq = 0.f;
    for (int r = 0; r < 128; r++){
        float v = hid[(size_t)(s*128+r)*HID_ + j];
        sum += v; sq = fmaf(v, v, sq);
    }
    d_bnsum[s*HID_ + j] = sum;
    d_bnsq [s*HID_ + j] = sq;
}

__global__ void bn_final(const float* __restrict__ gamma, const float* __restrict__ beta){
    int j = threadIdx.x;
    float sum = 0.f, sq = 0.f;
    for (int s = 0; s < 64; s++){ sum += d_bnsum[s*HID_+j]; sq += d_bnsq[s*HID_+j]; }
    float mu  = sum / (float)N_;
    float var = sq / (float)N_ - mu*mu;          // biased
    float sc  = gamma[j] * rsqrtf(var + EPS_);
    d_scale[j] = sc;
    d_shift[j] = beta[j] - mu*sc;
}

// ---------------- head: relu(BN(hidden)) @ Mw + Mb, log_softmax ----------------
__global__ __launch_bounds__(256) void final_kernel(const float* __restrict__ hid,
                                                    const float* __restrict__ Mw,
                                                    const float* __restrict__ Mb,
                                                    float* __restrict__ logits_out){
    __shared__ float h[4*260];
    __shared__ float lg[4*COUT_];
    __shared__ float lz[4];
    int r0 = blockIdx.x * 4;
    int tid = threadIdx.x;
    #pragma unroll
    for (int r = 0; r < 4; r++){
        float v = hid[(size_t)(r0+r)*HID_ + tid];
        h[r*260 + tid] = fmaxf(fmaf(v, d_scale[tid], d_shift[tid]), 0.f);
    }
    __syncthreads();
    if (tid < 4*COUT_){
        int row = tid / COUT_;
        int o   = tid - row*COUT_;
        float a = Mb[o];
        #pragma unroll 4
        for (int c = 0; c < HID_; c++)
            a = fmaf(h[row*260 + c], Mw[c*COUT_ + o], a);
        lg[tid] = a;
    }
    __syncthreads();
    if (tid < 4){
        float mx = -1e30f;
        for (int o = 0; o < COUT_; o++) mx = fmaxf(mx, lg[tid*COUT_+o]);
        float s = 0.f;
        for (int o = 0; o < COUT_; o++) s += expf(lg[tid*COUT_+o]-mx);
        lz[tid] = mx + logf(s);
    }
    __syncthreads();
    if (tid < 4*COUT_){
        int row = tid / COUT_;
        logits_out[(size_t)r0*COUT_ + tid] = lg[tid] - lz[row];
    }
}

// ---------------- launch ----------------
extern "C" void kernel_launch(void* const* d_in, const int* in_sizes, int n_in,
                              void* d_out, int out_size){
    const float* X     = (const float*)d_in[0];
    const float* La    = (const float*)d_in[1];
    const float* U     = (const float*)d_in[2];
    const float* eW1   = (const float*)d_in[3];
    const float* eb1   = (const float*)d_in[4];
    const float* eW2   = (const float*)d_in[5];
    const float* eb2   = (const float*)d_in[6];
    const float* eW3   = (const float*)d_in[7];
    const float* eb3   = (const float*)d_in[8];
    const float* gW1   = (const float*)d_in[9];
    const float* gb1   = (const float*)d_in[10];
    const float* gW2   = (const float*)d_in[11];
    const float* gb2   = (const float*)d_in[12];
    const float* Ww    = (const float*)d_in[13];
    const float* Wb    = (const float*)d_in[14];
    const float* gamma = (const float*)d_in[15];
    const float* beta  = (const float*)d_in[16];
    const float* Mw    = (const float*)d_in[17];
    const float* Mb    = (const float*)d_in[18];

    float* outF   = (float*)d_out;
    float* logits = outF;                              // [N, COUT]
    float* hidden = outF + (size_t)N_*COUT_;           // [N, HID]

    gate_kernel<<<1, 32>>>(La, gW1, gb1, gW2, gb2);
    lut_kernel<<<dim3(TLUT/128, E_), 128>>>(eW1, eb1, eW2, eb2, eW3, eb3);
    gemmD<<<dim3(CIN_/128, K_/40, NS_), 256>>>(U, X);
    vs_kernel<<<K_, 256>>>(U);
    reduceP_kernel<<<K_, 256>>>(Ww);
    gemmE<<<dim3(HID_/128, N_/64), 256>>>(U, Wb, hidden);
    bn_partial<<<64, 256>>>(hidden);
    bn_final<<<1, HID_>>>(gamma, beta);
    final_kernel<<<N_/4, 256>>>(hidden, Mw, Mb, logits);
}

// round 4
// speedup vs baseline: 1.1435x; 1.1435x over previous
#include <cuda_runtime.h>
#include <math.h>

#define N_    8192
#define K_    200
#define CIN_  512
#define HID_  256
#define COUT_ 40
#define E_    5
#define MH_   64
#define KG_   40
#define TLUT  4096
#define NS_   16
#define EPS_  1e-5f

// ---------------- device scratch (no allocation allowed) ----------------
__device__ __align__(16) float d_g[E_];
__device__ __align__(16) float d_lut[E_*TLUT];
__device__ __align__(16) float d_vpart[256*K_];
__device__ __align__(16) float d_Mpart[(size_t)NS_*256*CIN_];   // split-N partials of U^T X (k padded to 256)
__device__ __align__(16) float d_P[K_*HID_];                    // s * (U^T X) Ww
__device__ __align__(16) float d_bnsum[128*HID_];
__device__ __align__(16) float d_bnsq[128*HID_];
__device__ __align__(16) float d_scale[HID_];
__device__ __align__(16) float d_shift[HID_];

// ---------------- tf32 helpers ----------------
__device__ __forceinline__ void split_tf32(float v, float& hi, float& lo){
    unsigned h; asm("cvt.rna.tf32.f32 %0, %1;" : "=r"(h) : "f"(v));
    float hf = __uint_as_float(h);
    float r = v - hf;
    unsigned l; asm("cvt.rna.tf32.f32 %0, %1;" : "=r"(l) : "f"(r));
    hi = hf; lo = __uint_as_float(l);
}

__device__ __forceinline__ void mma_tf32(float* d, const unsigned* a, const unsigned* b){
    asm volatile(
        "mma.sync.aligned.m16n8k8.row.col.f32.tf32.tf32.f32 "
        "{%0,%1,%2,%3},{%4,%5,%6,%7},{%8,%9},{%0,%1,%2,%3};"
        : "+f"(d[0]), "+f"(d[1]), "+f"(d[2]), "+f"(d[3])
        : "r"(a[0]), "r"(a[1]), "r"(a[2]), "r"(a[3]), "r"(b[0]), "r"(b[1]));
}

// ---------------- gate ----------------
__global__ void gate_kernel(const float* __restrict__ La, const float* __restrict__ gW1,
                            const float* __restrict__ gb1, const float* __restrict__ gW2,
                            const float* __restrict__ gb2){
    if (threadIdx.x != 0) return;
    float stats[E_];
    for (int e = 0; e < E_; e++){
        float s = 0.f;
        for (int i = 0; i < KG_; i++) s += La[e*KG_ + i];
        stats[e] = s / (float)KG_;
    }
    float t1[E_];
    for (int j = 0; j < E_; j++){
        float z = gb1[j];
        for (int i = 0; i < E_; i++) z += stats[i]*gW1[i*E_+j];
        t1[j] = fmaxf(z, 0.f);
    }
    float t2[E_]; float mx = -1e30f;
    for (int j = 0; j < E_; j++){
        float z = gb2[j];
        for (int i = 0; i < E_; i++) z += t1[i]*gW2[i*E_+j];
        t2[j] = z; mx = fmaxf(mx, z);
    }
    float den = 0.f;
    for (int j = 0; j < E_; j++){ t2[j] = expf(t2[j]-mx); den += t2[j]; }
    for (int j = 0; j < E_; j++) d_g[j] = t2[j]/den;
}

// ---------------- LUT build: f_e(u) on [-8,8], TLUT points ----------------
__global__ __launch_bounds__(128) void lut_kernel(
        const float* __restrict__ eW1, const float* __restrict__ eb1,
        const float* __restrict__ eW2, const float* __restrict__ eb2,
        const float* __restrict__ eW3, const float* __restrict__ eb3){
    int e = blockIdx.y;
    __shared__ __align__(16) float w2t[MH_*MH_];
    __shared__ float w1[MH_], b1[MH_], b2s[MH_], w3[MH_];
    for (int i = threadIdx.x; i < MH_*MH_; i += blockDim.x){
        int h = i >> 6, g = i & 63;
        w2t[g*MH_ + h] = eW2[(e*MH_ + h)*MH_ + g];
    }
    if (threadIdx.x < MH_){
        int t = threadIdx.x;
        w1[t]  = eW1[e*MH_+t];
        b1[t]  = eb1[e*MH_+t];
        b2s[t] = eb2[e*MH_+t];
        w3[t]  = eW3[e*MH_+t];
    }
    __syncthreads();
    int j = blockIdx.x*blockDim.x + threadIdx.x;
    float u = -8.f + 16.f*(float)j/(float)(TLUT-1);
    float h1[MH_];
    #pragma unroll
    for (int h = 0; h < MH_; h++) h1[h] = fmaxf(fmaf(u, w1[h], b1[h]), 0.f);
    float acc = eb3[e];
    #pragma unroll 2
    for (int g = 0; g < MH_; g++){
        float z = b2s[g];
        const float4* row = (const float4*)(w2t + g*MH_);
        #pragma unroll
        for (int q = 0; q < 16; q++){
            float4 w = row[q];
            z = fmaf(h1[4*q+0], w.x, z);
            z = fmaf(h1[4*q+1], w.y, z);
            z = fmaf(h1[4*q+2], w.z, z);
            z = fmaf(h1[4*q+3], w.w, z);
        }
        acc = fmaf(fmaxf(z, 0.f), w3[g], acc);
    }
    d_lut[e*TLUT + j] = acc;
}

// ---------------- vs partials: row-coalesced, 256 blocks x 32 rows ----------------
__global__ __launch_bounds__(256) void vs_kernel(const float* __restrict__ U){
    int b = blockIdx.x;
    int col = threadIdx.x;
    if (col >= K_) return;
    int e = col / KG_;
    const float* lut = d_lut + e*TLUT;
    const float invd = (float)(TLUT-1)/16.f;
    float sum = 0.f;
    #pragma unroll 4
    for (int r = 0; r < 32; r++){
        float u = U[(size_t)(b*32+r)*K_ + col];
        float tt = (u + 8.f)*invd;
        int i = (int)floorf(tt);
        i = min(max(i, 0), TLUT-2);
        float fr = tt - (float)i;
        float a = __ldg(lut + i);
        float bb = __ldg(lut + i + 1);
        sum += a + (bb - a)*fr;
    }
    d_vpart[b*K_ + col] = sum;
}

// ---------------- gemmD: Mpart[z] = U[z]^T @ X[z] via 3xTF32 HMMA ----------------
// C tile 128(m=k-idx) x 128(n=c-idx); 8 warps (2x4); warp 64x32; contraction 512 per z
#define DPAD 136
__global__ __launch_bounds__(256) void gemmD_tc(const float* __restrict__ U, const float* __restrict__ X){
    __shared__ float Ah[16][DPAD], Al[16][DPAD], Bh[16][DPAD], Bl[16][DPAD];
    int n0 = blockIdx.x*128;
    int m0 = blockIdx.y*128;
    int rbase = blockIdx.z*512;
    int tid = threadIdx.x;
    int lane = tid & 31, warp = tid >> 5;
    int wm = warp >> 2, wn = warp & 3;
    int g = lane >> 2, t = lane & 3;

    float acc[4][4][4];
    #pragma unroll
    for (int i = 0; i < 4; i++)
        #pragma unroll
        for (int j = 0; j < 4; j++){
            acc[i][j][0]=0.f; acc[i][j][1]=0.f; acc[i][j][2]=0.f; acc[i][j][3]=0.f;
        }

    for (int s = 0; s < 32; s++){
        int row = rbase + s*16;
        #pragma unroll
        for (int j = 0; j < 2; j++){
            int slot = tid + j*256;
            int kk = slot >> 5;
            int c4 = (slot & 31) * 4;
            float4 v = make_float4(0.f,0.f,0.f,0.f);
            if (m0 + c4 < K_) v = *(const float4*)(U + (size_t)(row+kk)*K_ + m0 + c4);
            float h, l;
            split_tf32(v.x, h, l); Ah[kk][c4+0]=h; Al[kk][c4+0]=l;
            split_tf32(v.y, h, l); Ah[kk][c4+1]=h; Al[kk][c4+1]=l;
            split_tf32(v.z, h, l); Ah[kk][c4+2]=h; Al[kk][c4+2]=l;
            split_tf32(v.w, h, l); Ah[kk][c4+3]=h; Al[kk][c4+3]=l;
            float4 xv = *(const float4*)(X + (size_t)(row+kk)*CIN_ + n0 + c4);
            split_tf32(xv.x, h, l); Bh[kk][c4+0]=h; Bl[kk][c4+0]=l;
            split_tf32(xv.y, h, l); Bh[kk][c4+1]=h; Bl[kk][c4+1]=l;
            split_tf32(xv.z, h, l); Bh[kk][c4+2]=h; Bl[kk][c4+2]=l;
            split_tf32(xv.w, h, l); Bh[kk][c4+3]=h; Bl[kk][c4+3]=l;
        }
        __syncthreads();
        #pragma unroll
        for (int ks = 0; ks < 2; ks++){
            int c = ks*8 + t;
            unsigned ah[4][4], al[4][4];
            #pragma unroll
            for (int mf = 0; mf < 4; mf++){
                int m = wm*64 + mf*16 + g;
                ah[mf][0] = __float_as_uint(Ah[c  ][m  ]);
                ah[mf][1] = __float_as_uint(Ah[c  ][m+8]);
                ah[mf][2] = __float_as_uint(Ah[c+4][m  ]);
                ah[mf][3] = __float_as_uint(Ah[c+4][m+8]);
                al[mf][0] = __float_as_uint(Al[c  ][m  ]);
                al[mf][1] = __float_as_uint(Al[c  ][m+8]);
                al[mf][2] = __float_as_uint(Al[c+4][m  ]);
                al[mf][3] = __float_as_uint(Al[c+4][m+8]);
            }
            #pragma unroll
            for (int nf = 0; nf < 4; nf++){
                int n = wn*32 + nf*8 + g;
                unsigned bh[2] = { __float_as_uint(Bh[c][n]), __float_as_uint(Bh[c+4][n]) };
                unsigned bl[2] = { __float_as_uint(Bl[c][n]), __float_as_uint(Bl[c+4][n]) };
                #pragma unroll
                for (int mf = 0; mf < 4; mf++){
                    mma_tf32(acc[mf][nf], ah[mf], bh);
                    mma_tf32(acc[mf][nf], al[mf], bh);
                    mma_tf32(acc[mf][nf], ah[mf], bl);
                }
            }
        }
        __syncthreads();
    }
    float* out = d_Mpart + (size_t)blockIdx.z*256*CIN_;
    #pragma unroll
    for (int mf = 0; mf < 4; mf++){
        #pragma unroll
        for (int nf = 0; nf < 4; nf++){
            int m = m0 + wm*64 + mf*16 + g;
            int n = n0 + wn*32 + nf*8 + 2*t;
            float2 v0 = make_float2(acc[mf][nf][0], acc[mf][nf][1]);
            float2 v1 = make_float2(acc[mf][nf][2], acc[mf][nf][3]);
            *(float2*)(out + (size_t)m*CIN_ + n)     = v0;
            *(float2*)(out + (size_t)(m+8)*CIN_ + n) = v1;
        }
    }
}

// ---------------- P[k,:] = s[k] * (sum_z Mpart)[k,:] @ Ww ----------------
__global__ __launch_bounds__(256) void reduceP_kernel(const float* __restrict__ Ww){
    int k = blockIdx.x;
    __shared__ float m[CIN_];
    __shared__ float red[256];
    __shared__ float sk;
    // reduce vs partials -> s[k]
    float v = d_vpart[threadIdx.x*K_ + k];
    red[threadIdx.x] = v;
    __syncthreads();
    for (int off = 128; off > 0; off >>= 1){
        if (threadIdx.x < off) red[threadIdx.x] += red[threadIdx.x + off];
        __syncthreads();
    }
    if (threadIdx.x == 0) sk = d_g[k/KG_] * (red[0] / (float)N_);
    // reduce Mpart
    for (int c = threadIdx.x; c < CIN_; c += 256){
        float s = 0.f;
        #pragma unroll
        for (int b = 0; b < NS_; b++) s += d_Mpart[(size_t)b*256*CIN_ + (size_t)k*CIN_ + c];
        m[c] = s;
    }
    __syncthreads();
    int j = threadIdx.x;
    float a0=0.f, a1=0.f, a2=0.f, a3=0.f;
    for (int c = 0; c < CIN_; c += 4){
        a0 = fmaf(m[c+0], Ww[(c+0)*HID_+j], a0);
        a1 = fmaf(m[c+1], Ww[(c+1)*HID_+j], a1);
        a2 = fmaf(m[c+2], Ww[(c+2)*HID_+j], a2);
        a3 = fmaf(m[c+3], Ww[(c+3)*HID_+j], a3);
    }
    d_P[k*HID_ + j] = ((a0+a1)+(a2+a3)) * sk;
}

// ---------------- gemmE: hidden = U @ P + Wb via 3xTF32 HMMA ----------------
// C tile 256(m=node) x 64(n=hid); 8 warps (4x2); warp 64x32; K=200 (25 steps of 8)
#define EPADA 264
#define EPADB 72
__global__ __launch_bounds__(256) void gemmE_tc(const float* __restrict__ U, const float* __restrict__ Wb,
                                                float* __restrict__ hid){
    __shared__ float Ah[8][EPADA], Al[8][EPADA], Bh[8][EPADB], Bl[8][EPADB];
    __shared__ float wbs[64];
    int m0 = blockIdx.x*256;
    int n0 = blockIdx.y*64;
    int tid = threadIdx.x;
    int lane = tid & 31, warp = tid >> 5;
    int wm = warp >> 1, wn = warp & 1;
    int g = lane >> 2, t = lane & 3;
    if (tid < 64) wbs[tid] = Wb[n0 + tid];

    float acc[4][4][4];
    #pragma unroll
    for (int i = 0; i < 4; i++)
        #pragma unroll
        for (int j = 0; j < 4; j++){
            acc[i][j][0]=0.f; acc[i][j][1]=0.f; acc[i][j][2]=0.f; acc[i][j][3]=0.f;
        }

    for (int s = 0; s < 25; s++){
        int k0 = s*8;
        {
            const float* p = U + (size_t)(m0 + tid)*K_ + k0;
            float4 v0 = *(const float4*)p;
            float4 v1 = *(const float4*)(p + 4);
            float h, l;
            split_tf32(v0.x, h, l); Ah[0][tid]=h; Al[0][tid]=l;
            split_tf32(v0.y, h, l); Ah[1][tid]=h; Al[1][tid]=l;
            split_tf32(v0.z, h, l); Ah[2][tid]=h; Al[2][tid]=l;
            split_tf32(v0.w, h, l); Ah[3][tid]=h; Al[3][tid]=l;
            split_tf32(v1.x, h, l); Ah[4][tid]=h; Al[4][tid]=l;
            split_tf32(v1.y, h, l); Ah[5][tid]=h; Al[5][tid]=l;
            split_tf32(v1.z, h, l); Ah[6][tid]=h; Al[6][tid]=l;
            split_tf32(v1.w, h, l); Ah[7][tid]=h; Al[7][tid]=l;
        }
        if (tid < 128){
            int kk = tid >> 4;
            int c4 = (tid & 15) * 4;
            float4 v = *(const float4*)(d_P + (size_t)(k0+kk)*HID_ + n0 + c4);
            float h, l;
            split_tf32(v.x, h, l); Bh[kk][c4+0]=h; Bl[kk][c4+0]=l;
            split_tf32(v.y, h, l); Bh[kk][c4+1]=h; Bl[kk][c4+1]=l;
            split_tf32(v.z, h, l); Bh[kk][c4+2]=h; Bl[kk][c4+2]=l;
            split_tf32(v.w, h, l); Bh[kk][c4+3]=h; Bl[kk][c4+3]=l;
        }
        __syncthreads();
        unsigned ah[4][4], al[4][4];
        #pragma unroll
        for (int mf = 0; mf < 4; mf++){
            int m = wm*64 + mf*16 + g;
            ah[mf][0] = __float_as_uint(Ah[t  ][m  ]);
            ah[mf][1] = __float_as_uint(Ah[t  ][m+8]);
            ah[mf][2] = __float_as_uint(Ah[t+4][m  ]);
            ah[mf][3] = __float_as_uint(Ah[t+4][m+8]);
            al[mf][0] = __float_as_uint(Al[t  ][m  ]);
            al[mf][1] = __float_as_uint(Al[t  ][m+8]);
            al[mf][2] = __float_as_uint(Al[t+4][m  ]);
            al[mf][3] = __float_as_uint(Al[t+4][m+8]);
        }
        #pragma unroll
        for (int nf = 0; nf < 4; nf++){
            int n = wn*32 + nf*8 + g;
            unsigned bh[2] = { __float_as_uint(Bh[t][n]), __float_as_uint(Bh[t+4][n]) };
            unsigned bl[2] = { __float_as_uint(Bl[t][n]), __float_as_uint(Bl[t+4][n]) };
            #pragma unroll
            for (int mf = 0; mf < 4; mf++){
                mma_tf32(acc[mf][nf], ah[mf], bh);
                mma_tf32(acc[mf][nf], al[mf], bh);
                mma_tf32(acc[mf][nf], ah[mf], bl);
            }
        }
        __syncthreads();
    }
    #pragma unroll
    for (int mf = 0; mf < 4; mf++){
        #pragma unroll
        for (int nf = 0; nf < 4; nf++){
            int m = m0 + wm*64 + mf*16 + g;
            int nl = wn*32 + nf*8 + 2*t;
            float2 v0 = make_float2(acc[mf][nf][0] + wbs[nl], acc[mf][nf][1] + wbs[nl+1]);
            float2 v1 = make_float2(acc[mf][nf][2] + wbs[nl], acc[mf][nf][3] + wbs[nl+1]);
            *(float2*)(hid + (size_t)m*HID_ + n0 + nl)     = v0;
            *(float2*)(hid + (size_t)(m+8)*HID_ + n0 + nl) = v1;
        }
    }
}

// ---------------- BN stats ----------------
__global__ __launch_bounds__(256) void bn_partial(const float* __restrict__ hid){
    int j = threadIdx.x;
    int b = blockIdx.x;               // 128 blocks x 64 rows
    float sum = 0.f, sq = 0.f;
    #pragma unroll 4
    for (int r = 0; r < 64; r++){
        float v = hid[(size_t)(b*64+r)*HID_ + j];
        sum += v; sq = fmaf(v, v, sq);
    }
    d_bnsum[b*HID_ + j] = sum;
    d_bnsq [b*HID_ + j] = sq;
}

__global__ void bn_final(const float* __restrict__ gamma, const float* __restrict__ beta){
    int j = threadIdx.x;
    float sum = 0.f, sq = 0.f;
    for (int s = 0; s < 128; s++){ sum += d_bnsum[s*HID_+j]; sq += d_bnsq[s*HID_+j]; }
    float mu  = sum / (float)N_;
    float var = sq / (float)N_ - mu*mu;
    float sc  = gamma[j] * rsqrtf(var + EPS_);
    d_scale[j] = sc;
    d_shift[j] = beta[j] - mu*sc;
}

// ---------------- head ----------------
__global__ __launch_bounds__(256) void final_kernel(const float* __restrict__ hid,
                                                    const float* __restrict__ Mw,
                                                    const float* __restrict__ Mb,
                                                    float* __restrict__ logits_out){
    __shared__ float h[4*260];
    __shared__ float lg[4*COUT_];
    __shared__ float lz[4];
    int r0 = blockIdx.x * 4;
    int tid = threadIdx.x;
    #pragma unroll
    for (int r = 0; r < 4; r++){
        float v = hid[(size_t)(r0+r)*HID_ + tid];
        h[r*260 + tid] = fmaxf(fmaf(v, d_scale[tid], d_shift[tid]), 0.f);
    }
    __syncthreads();
    if (tid < 4*COUT_){
        int row = tid / COUT_;
        int o   = tid - row*COUT_;
        float a = Mb[o];
        #pragma unroll 4
        for (int c = 0; c < HID_; c++)
            a = fmaf(h[row*260 + c], Mw[c*COUT_ + o], a);
        lg[tid] = a;
    }
    __syncthreads();
    if (tid < 4){
        float mx = -1e30f;
        for (int o = 0; o < COUT_; o++) mx = fmaxf(mx, lg[tid*COUT_+o]);
        float s = 0.f;
        for (int o = 0; o < COUT_; o++) s += expf(lg[tid*COUT_+o]-mx);
        lz[tid] = mx + logf(s);
    }
    __syncthreads();
    if (tid < 4*COUT_){
        int row = tid / COUT_;
        logits_out[(size_t)r0*COUT_ + tid] = lg[tid] - lz[row];
    }
}

// ---------------- launch ----------------
extern "C" void kernel_launch(void* const* d_in, const int* in_sizes, int n_in,
                              void* d_out, int out_size){
    const float* X     = (const float*)d_in[0];
    const float* La    = (const float*)d_in[1];
    const float* U     = (const float*)d_in[2];
    const float* eW1   = (const float*)d_in[3];
    const float* eb1   = (const float*)d_in[4];
    const float* eW2   = (const float*)d_in[5];
    const float* eb2   = (const float*)d_in[6];
    const float* eW3   = (const float*)d_in[7];
    const float* eb3   = (const float*)d_in[8];
    const float* gW1   = (const float*)d_in[9];
    const float* gb1   = (const float*)d_in[10];
    const float* gW2   = (const float*)d_in[11];
    const float* gb2   = (const float*)d_in[12];
    const float* Ww    = (const float*)d_in[13];
    const float* Wb    = (const float*)d_in[14];
    const float* gamma = (const float*)d_in[15];
    const float* beta  = (const float*)d_in[16];
    const float* Mw    = (const float*)d_in[17];
    const float* Mb    = (const float*)d_in[18];

    float* outF   = (float*)d_out;
    float* logits = outF;                              // [N, COUT]
    float* hidden = outF + (size_t)N_*COUT_;           // [N, HID]

    gate_kernel<<<1, 32>>>(La, gW1, gb1, gW2, gb2);
    lut_kernel<<<dim3(TLUT/128, E_), 128>>>(eW1, eb1, eW2, eb2, eW3, eb3);
    gemmD_tc<<<dim3(CIN_/128, 2, NS_), 256>>>(U, X);
    vs_kernel<<<256, 256>>>(U);
    reduceP_kernel<<<K_, 256>>>(Ww);
    gemmE_tc<<<dim3(N_/256, HID_/64), 256>>>(U, Wb, hidden);
    bn_partial<<<128, 256>>>(hidden);
    bn_final<<<1, HID_>>>(gamma, beta);
    final_kernel<<<N_/4, 256>>>(hidden, Mw, Mb, logits);
}

// round 5
// speedup vs baseline: 1.2331x; 1.0783x over previous
#include <cuda_runtime.h>
#include <math.h>

#define N_    8192
#define K_    200
#define CIN_  512
#define HID_  256
#define COUT_ 40
#define E_    5
#define MH_   64
#define KG_   40
#define TLUT  4096
#define NS_   16
#define EPS_  1e-5f

// ---------------- device scratch ----------------
__device__ __align__(16) float d_g[E_];
__device__ __align__(16) float d_lut[E_*TLUT];
__device__ __align__(16) float d_vpart[1024*K_];
__device__ __align__(16) float d_Mpart[(size_t)NS_*256*CIN_];
__device__ __align__(16) float d_P[K_*HID_];
__device__ __align__(16) float d_bnsum[256*HID_];
__device__ __align__(16) float d_bnsq[256*HID_];
__device__ __align__(16) float d_scale[HID_];
__device__ __align__(16) float d_shift[HID_];

// ---------------- tf32 helpers ----------------
__device__ __forceinline__ void split_tf32(float v, float& hi, float& lo){
    unsigned h; asm("cvt.rna.tf32.f32 %0, %1;" : "=r"(h) : "f"(v));
    float hf = __uint_as_float(h);
    float r = v - hf;
    unsigned l; asm("cvt.rna.tf32.f32 %0, %1;" : "=r"(l) : "f"(r));
    hi = hf; lo = __uint_as_float(l);
}

__device__ __forceinline__ void mma_tf32(float* d, const unsigned* a, const unsigned* b){
    asm volatile(
        "mma.sync.aligned.m16n8k8.row.col.f32.tf32.tf32.f32 "
        "{%0,%1,%2,%3},{%4,%5,%6,%7},{%8,%9},{%0,%1,%2,%3};"
        : "+f"(d[0]), "+f"(d[1]), "+f"(d[2]), "+f"(d[3])
        : "r"(a[0]), "r"(a[1]), "r"(a[2]), "r"(a[3]), "r"(b[0]), "r"(b[1]));
}

// ---------------- LUT build + gate (fused) ----------------
__global__ __launch_bounds__(128) void lutgate_kernel(
        const float* __restrict__ eW1, const float* __restrict__ eb1,
        const float* __restrict__ eW2, const float* __restrict__ eb2,
        const float* __restrict__ eW3, const float* __restrict__ eb3,
        const float* __restrict__ La,  const float* __restrict__ gW1,
        const float* __restrict__ gb1, const float* __restrict__ gW2,
        const float* __restrict__ gb2){
    int e = blockIdx.y;
    __shared__ __align__(16) float w2t[MH_*MH_];
    __shared__ float w1[MH_], b1[MH_], b2s[MH_], w3[MH_];
    for (int i = threadIdx.x; i < MH_*MH_; i += blockDim.x){
        int h = i >> 6, g = i & 63;
        w2t[g*MH_ + h] = eW2[(e*MH_ + h)*MH_ + g];
    }
    if (threadIdx.x < MH_){
        int t = threadIdx.x;
        w1[t]  = eW1[e*MH_+t];
        b1[t]  = eb1[e*MH_+t];
        b2s[t] = eb2[e*MH_+t];
        w3[t]  = eW3[e*MH_+t];
    }
    __syncthreads();
    int j = blockIdx.x*blockDim.x + threadIdx.x;
    float u = -8.f + 16.f*(float)j/(float)(TLUT-1);
    float h1[MH_];
    #pragma unroll
    for (int h = 0; h < MH_; h++) h1[h] = fmaxf(fmaf(u, w1[h], b1[h]), 0.f);
    float acc = eb3[e];
    #pragma unroll 2
    for (int g = 0; g < MH_; g++){
        float z = b2s[g];
        const float4* row = (const float4*)(w2t + g*MH_);
        #pragma unroll
        for (int q = 0; q < 16; q++){
            float4 w = row[q];
            z = fmaf(h1[4*q+0], w.x, z);
            z = fmaf(h1[4*q+1], w.y, z);
            z = fmaf(h1[4*q+2], w.z, z);
            z = fmaf(h1[4*q+3], w.w, z);
        }
        acc = fmaf(fmaxf(z, 0.f), w3[g], acc);
    }
    d_lut[e*TLUT + j] = acc;

    // gate, once
    if (blockIdx.x == 0 && blockIdx.y == 0 && threadIdx.x == 0){
        float stats[E_];
        for (int ee = 0; ee < E_; ee++){
            float s = 0.f;
            for (int i = 0; i < KG_; i++) s += La[ee*KG_ + i];
            stats[ee] = s / (float)KG_;
        }
        float t1[E_];
        for (int jj = 0; jj < E_; jj++){
            float z = gb1[jj];
            for (int i = 0; i < E_; i++) z += stats[i]*gW1[i*E_+jj];
            t1[jj] = fmaxf(z, 0.f);
        }
        float t2[E_]; float mx = -1e30f;
        for (int jj = 0; jj < E_; jj++){
            float z = gb2[jj];
            for (int i = 0; i < E_; i++) z += t1[i]*gW2[i*E_+jj];
            t2[jj] = z; mx = fmaxf(mx, z);
        }
        float den = 0.f;
        for (int jj = 0; jj < E_; jj++){ t2[jj] = expf(t2[jj]-mx); den += t2[jj]; }
        for (int jj = 0; jj < E_; jj++) d_g[jj] = t2[jj]/den;
    }
}

// ---------------- vs partials: 1024 blocks x 8 rows ----------------
__global__ __launch_bounds__(256) void vs_kernel(const float* __restrict__ U){
    int b = blockIdx.x;
    int col = threadIdx.x;
    if (col >= K_) return;
    int e = col / KG_;
    const float* lut = d_lut + e*TLUT;
    const float invd = (float)(TLUT-1)/16.f;
    float sum = 0.f;
    #pragma unroll
    for (int r = 0; r < 8; r++){
        float u = U[(size_t)(b*8+r)*K_ + col];
        float tt = (u + 8.f)*invd;
        int i = (int)floorf(tt);
        i = min(max(i, 0), TLUT-2);
        float fr = tt - (float)i;
        float a = __ldg(lut + i);
        float bb = __ldg(lut + i + 1);
        sum += a + (bb - a)*fr;
    }
    d_vpart[b*K_ + col] = sum;
}

// ---------------- gemmD: Mpart[z] = U[z]^T @ X[z], 3xTF32, double-buffered ----------------
// tile 128m x 128n, k-chunk 8, 64 stages of 8 rows; 8 warps (2x4), warp 64x32
#define DPAD 136
__global__ __launch_bounds__(256) void gemmD_tc(const float* __restrict__ U, const float* __restrict__ X){
    __shared__ float Ah[2][8][DPAD], Al[2][8][DPAD], Bh[2][8][DPAD], Bl[2][8][DPAD];
    int n0 = blockIdx.x*128;
    int m0 = blockIdx.y*128;
    int rbase = blockIdx.z*512;
    int tid = threadIdx.x;
    int lane = tid & 31, warp = tid >> 5;
    int wm = warp >> 2, wn = warp & 3;
    int g = lane >> 2, t = lane & 3;
    int kk = tid >> 5;             // 0..7 (contraction row within stage)
    int c4 = (tid & 31) * 4;       // column quad
    bool aval = (m0 + c4 < K_);

    float acc[4][4][4];
    #pragma unroll
    for (int i = 0; i < 4; i++)
        #pragma unroll
        for (int j = 0; j < 4; j++){
            acc[i][j][0]=0.f; acc[i][j][1]=0.f; acc[i][j][2]=0.f; acc[i][j][3]=0.f;
        }

    float4 uv, xv;
    auto LOAD = [&](int s){
        int row = rbase + s*8 + kk;
        uv = aval ? *(const float4*)(U + (size_t)row*K_ + m0 + c4)
                  : make_float4(0.f,0.f,0.f,0.f);
        xv = *(const float4*)(X + (size_t)row*CIN_ + n0 + c4);
    };
    auto STORE = [&](int p){
        float h, l;
        split_tf32(uv.x, h, l); Ah[p][kk][c4+0]=h; Al[p][kk][c4+0]=l;
        split_tf32(uv.y, h, l); Ah[p][kk][c4+1]=h; Al[p][kk][c4+1]=l;
        split_tf32(uv.z, h, l); Ah[p][kk][c4+2]=h; Al[p][kk][c4+2]=l;
        split_tf32(uv.w, h, l); Ah[p][kk][c4+3]=h; Al[p][kk][c4+3]=l;
        split_tf32(xv.x, h, l); Bh[p][kk][c4+0]=h; Bl[p][kk][c4+0]=l;
        split_tf32(xv.y, h, l); Bh[p][kk][c4+1]=h; Bl[p][kk][c4+1]=l;
        split_tf32(xv.z, h, l); Bh[p][kk][c4+2]=h; Bl[p][kk][c4+2]=l;
        split_tf32(xv.w, h, l); Bh[p][kk][c4+3]=h; Bl[p][kk][c4+3]=l;
    };

    LOAD(0); STORE(0);
    __syncthreads();

    for (int s = 0; s < 64; s++){
        int p = s & 1;
        if (s < 63) LOAD(s+1);

        unsigned ah[4][4], al[4][4];
        #pragma unroll
        for (int mf = 0; mf < 4; mf++){
            int m = wm*64 + mf*16 + g;
            ah[mf][0] = __float_as_uint(Ah[p][t  ][m  ]);
            ah[mf][1] = __float_as_uint(Ah[p][t  ][m+8]);
            ah[mf][2] = __float_as_uint(Ah[p][t+4][m  ]);
            ah[mf][3] = __float_as_uint(Ah[p][t+4][m+8]);
            al[mf][0] = __float_as_uint(Al[p][t  ][m  ]);
            al[mf][1] = __float_as_uint(Al[p][t  ][m+8]);
            al[mf][2] = __float_as_uint(Al[p][t+4][m  ]);
            al[mf][3] = __float_as_uint(Al[p][t+4][m+8]);
        }
        #pragma unroll
        for (int nf = 0; nf < 4; nf++){
            int n = wn*32 + nf*8 + g;
            unsigned bh[2] = { __float_as_uint(Bh[p][t][n]), __float_as_uint(Bh[p][t+4][n]) };
            unsigned bl[2] = { __float_as_uint(Bl[p][t][n]), __float_as_uint(Bl[p][t+4][n]) };
            #pragma unroll
            for (int mf = 0; mf < 4; mf++){
                mma_tf32(acc[mf][nf], ah[mf], bh);
                mma_tf32(acc[mf][nf], al[mf], bh);
                mma_tf32(acc[mf][nf], ah[mf], bl);
            }
        }
        if (s < 63) STORE(p ^ 1);
        __syncthreads();
    }

    float* out = d_Mpart + (size_t)blockIdx.z*256*CIN_;
    #pragma unroll
    for (int mf = 0; mf < 4; mf++){
        #pragma unroll
        for (int nf = 0; nf < 4; nf++){
            int m = m0 + wm*64 + mf*16 + g;
            int n = n0 + wn*32 + nf*8 + 2*t;
            float2 v0 = make_float2(acc[mf][nf][0], acc[mf][nf][1]);
            float2 v1 = make_float2(acc[mf][nf][2], acc[mf][nf][3]);
            *(float2*)(out + (size_t)m*CIN_ + n)     = v0;
            *(float2*)(out + (size_t)(m+8)*CIN_ + n) = v1;
        }
    }
}

// ---------------- P[k,:] = s[k] * (sum_z Mpart)[k,:] @ Ww ----------------
__global__ __launch_bounds__(256) void reduceP_kernel(const float* __restrict__ Ww){
    int k = blockIdx.x;
    __shared__ float m[CIN_];
    __shared__ float red[256];
    __shared__ float sk;
    float v = 0.f;
    #pragma unroll
    for (int q = 0; q < 4; q++) v += d_vpart[(size_t)(threadIdx.x + q*256)*K_ + k];
    red[threadIdx.x] = v;
    __syncthreads();
    for (int off = 128; off > 0; off >>= 1){
        if (threadIdx.x < off) red[threadIdx.x] += red[threadIdx.x + off];
        __syncthreads();
    }
    if (threadIdx.x == 0) sk = d_g[k/KG_] * (red[0] / (float)N_);
    for (int c = threadIdx.x; c < CIN_; c += 256){
        float s = 0.f;
        #pragma unroll
        for (int b = 0; b < NS_; b++) s += d_Mpart[(size_t)b*256*CIN_ + (size_t)k*CIN_ + c];
        m[c] = s;
    }
    __syncthreads();
    int j = threadIdx.x;
    float a0=0.f, a1=0.f, a2=0.f, a3=0.f;
    for (int c = 0; c < CIN_; c += 4){
        a0 = fmaf(m[c+0], Ww[(c+0)*HID_+j], a0);
        a1 = fmaf(m[c+1], Ww[(c+1)*HID_+j], a1);
        a2 = fmaf(m[c+2], Ww[(c+2)*HID_+j], a2);
        a3 = fmaf(m[c+3], Ww[(c+3)*HID_+j], a3);
    }
    d_P[k*HID_ + j] = ((a0+a1)+(a2+a3)) * sk;
}

// ---------------- gemmE: hidden = U @ P + Wb, 3xTF32, double-buffered ----------------
// tile 256m x 64n; 8 warps (4x2), warp 64x32; 25 stages of k=8
#define EPADA 264
#define EPADB 72
__global__ __launch_bounds__(256) void gemmE_tc(const float* __restrict__ U, const float* __restrict__ Wb,
                                                float* __restrict__ hid){
    __shared__ float Ah[2][8][EPADA], Al[2][8][EPADA], Bh[2][8][EPADB], Bl[2][8][EPADB];
    __shared__ float wbs[64];
    int m0 = blockIdx.x*256;
    int n0 = blockIdx.y*64;
    int tid = threadIdx.x;
    int lane = tid & 31, warp = tid >> 5;
    int wm = warp >> 1, wn = warp & 1;
    int g = lane >> 2, t = lane & 3;
    if (tid < 64) wbs[tid] = Wb[n0 + tid];
    int bkk = tid >> 4;            // 0..15 (only tid<128 used)
    int bc4 = (tid & 15) * 4;

    float acc[4][4][4];
    #pragma unroll
    for (int i = 0; i < 4; i++)
        #pragma unroll
        for (int j = 0; j < 4; j++){
            acc[i][j][0]=0.f; acc[i][j][1]=0.f; acc[i][j][2]=0.f; acc[i][j][3]=0.f;
        }

    float4 av0, av1, bv;
    auto LOAD = [&](int s){
        const float* pa = U + (size_t)(m0 + tid)*K_ + s*8;
        av0 = *(const float4*)pa;
        av1 = *(const float4*)(pa + 4);
        if (tid < 128)
            bv = *(const float4*)(d_P + (size_t)(s*8 + bkk)*HID_ + n0 + bc4);
    };
    auto STORE = [&](int p){
        float h, l;
        split_tf32(av0.x, h, l); Ah[p][0][tid]=h; Al[p][0][tid]=l;
        split_tf32(av0.y, h, l); Ah[p][1][tid]=h; Al[p][1][tid]=l;
        split_tf32(av0.z, h, l); Ah[p][2][tid]=h; Al[p][2][tid]=l;
        split_tf32(av0.w, h, l); Ah[p][3][tid]=h; Al[p][3][tid]=l;
        split_tf32(av1.x, h, l); Ah[p][4][tid]=h; Al[p][4][tid]=l;
        split_tf32(av1.y, h, l); Ah[p][5][tid]=h; Al[p][5][tid]=l;
        split_tf32(av1.z, h, l); Ah[p][6][tid]=h; Al[p][6][tid]=l;
        split_tf32(av1.w, h, l); Ah[p][7][tid]=h; Al[p][7][tid]=l;
        if (tid < 128){
            split_tf32(bv.x, h, l); Bh[p][bkk][bc4+0]=h; Bl[p][bkk][bc4+0]=l;
            split_tf32(bv.y, h, l); Bh[p][bkk][bc4+1]=h; Bl[p][bkk][bc4+1]=l;
            split_tf32(bv.z, h, l); Bh[p][bkk][bc4+2]=h; Bl[p][bkk][bc4+2]=l;
            split_tf32(bv.w, h, l); Bh[p][bkk][bc4+3]=h; Bl[p][bkk][bc4+3]=l;
        }
    };

    LOAD(0); STORE(0);
    __syncthreads();

    for (int s = 0; s < 25; s++){
        int p = s & 1;
        if (s < 24) LOAD(s+1);

        unsigned ah[4][4], al[4][4];
        #pragma unroll
        for (int mf = 0; mf < 4; mf++){
            int m = wm*64 + mf*16 + g;
            ah[mf][0] = __float_as_uint(Ah[p][t  ][m  ]);
            ah[mf][1] = __float_as_uint(Ah[p][t  ][m+8]);
            ah[mf][2] = __float_as_uint(Ah[p][t+4][m  ]);
            ah[mf][3] = __float_as_uint(Ah[p][t+4][m+8]);
            al[mf][0] = __float_as_uint(Al[p][t  ][m  ]);
            al[mf][1] = __float_as_uint(Al[p][t  ][m+8]);
            al[mf][2] = __float_as_uint(Al[p][t+4][m  ]);
            al[mf][3] = __float_as_uint(Al[p][t+4][m+8]);
        }
        #pragma unroll
        for (int nf = 0; nf < 4; nf++){
            int n = wn*32 + nf*8 + g;
            unsigned bh[2] = { __float_as_uint(Bh[p][t][n]), __float_as_uint(Bh[p][t+4][n]) };
            unsigned bl[2] = { __float_as_uint(Bl[p][t][n]), __float_as_uint(Bl[p][t+4][n]) };
            #pragma unroll
            for (int mf = 0; mf < 4; mf++){
                mma_tf32(acc[mf][nf], ah[mf], bh);
                mma_tf32(acc[mf][nf], al[mf], bh);
                mma_tf32(acc[mf][nf], ah[mf], bl);
            }
        }
        if (s < 24) STORE(p ^ 1);
        __syncthreads();
    }

    #pragma unroll
    for (int mf = 0; mf < 4; mf++){
        #pragma unroll
        for (int nf = 0; nf < 4; nf++){
            int m = m0 + wm*64 + mf*16 + g;
            int nl = wn*32 + nf*8 + 2*t;
            float2 v0 = make_float2(acc[mf][nf][0] + wbs[nl], acc[mf][nf][1] + wbs[nl+1]);
            float2 v1 = make_float2(acc[mf][nf][2] + wbs[nl], acc[mf][nf][3] + wbs[nl+1]);
            *(float2*)(hid + (size_t)m*HID_ + n0 + nl)     = v0;
            *(float2*)(hid + (size_t)(m+8)*HID_ + n0 + nl) = v1;
        }
    }
}

// ---------------- BN stats ----------------
__global__ __launch_bounds__(256) void bn_partial(const float* __restrict__ hid){
    int j = threadIdx.x;
    int b = blockIdx.x;               // 256 blocks x 32 rows
    float sum = 0.f, sq = 0.f;
    #pragma unroll 4
    for (int r = 0; r < 32; r++){
        float v = hid[(size_t)(b*32+r)*HID_ + j];
        sum += v; sq = fmaf(v, v, sq);
    }
    d_bnsum[b*HID_ + j] = sum;
    d_bnsq [b*HID_ + j] = sq;
}

__global__ void bn_final(const float* __restrict__ gamma, const float* __restrict__ beta){
    int j = threadIdx.x;
    float sum = 0.f, sq = 0.f;
    for (int s = 0; s < 256; s++){ sum += d_bnsum[s*HID_+j]; sq += d_bnsq[s*HID_+j]; }
    float mu  = sum / (float)N_;
    float var = sq / (float)N_ - mu*mu;
    float sc  = gamma[j] * rsqrtf(var + EPS_);
    d_scale[j] = sc;
    d_shift[j] = beta[j] - mu*sc;
}

// ---------------- head: 8 rows per block ----------------
__global__ __launch_bounds__(256) void final_kernel(const float* __restrict__ hid,
                                                    const float* __restrict__ Mw,
                                                    const float* __restrict__ Mb,
                                                    float* __restrict__ logits_out){
    __shared__ float h[8*260];
    __shared__ float lg[8*COUT_];
    __shared__ float lz[8];
    int r0 = blockIdx.x * 8;
    int tid = threadIdx.x;
    #pragma unroll
    for (int r = 0; r < 8; r++){
        float v = hid[(size_t)(r0+r)*HID_ + tid];
        h[r*260 + tid] = fmaxf(fmaf(v, d_scale[tid], d_shift[tid]), 0.f);
    }
    __syncthreads();
    for (int base = 0; base < 8*COUT_; base += 256){
        int idx = base + tid;
        if (idx < 8*COUT_){
            int row = idx / COUT_;
            int o   = idx - row*COUT_;
            float a = Mb[o];
            #pragma unroll 4
            for (int c = 0; c < HID_; c++)
                a = fmaf(h[row*260 + c], Mw[c*COUT_ + o], a);
            lg[idx] = a;
        }
    }
    __syncthreads();
    if (tid < 8){
        float mx = -1e30f;
        for (int o = 0; o < COUT_; o++) mx = fmaxf(mx, lg[tid*COUT_+o]);
        float s = 0.f;
        for (int o = 0; o < COUT_; o++) s += expf(lg[tid*COUT_+o]-mx);
        lz[tid] = mx + logf(s);
    }
    __syncthreads();
    for (int base = 0; base < 8*COUT_; base += 256){
        int idx = base + tid;
        if (idx < 8*COUT_){
            int row = idx / COUT_;
            logits_out[(size_t)r0*COUT_ + idx] = lg[idx] - lz[row];
        }
    }
}

// ---------------- launch ----------------
extern "C" void kernel_launch(void* const* d_in, const int* in_sizes, int n_in,
                              void* d_out, int out_size){
    const float* X     = (const float*)d_in[0];
    const float* La    = (const float*)d_in[1];
    const float* U     = (const float*)d_in[2];
    const float* eW1   = (const float*)d_in[3];
    const float* eb1   = (const float*)d_in[4];
    const float* eW2   = (const float*)d_in[5];
    const float* eb2   = (const float*)d_in[6];
    const float* eW3   = (const float*)d_in[7];
    const float* eb3   = (const float*)d_in[8];
    const float* gW1   = (const float*)d_in[9];
    const float* gb1   = (const float*)d_in[10];
    const float* gW2   = (const float*)d_in[11];
    const float* gb2   = (const float*)d_in[12];
    const float* Ww    = (const float*)d_in[13];
    const float* Wb    = (const float*)d_in[14];
    const float* gamma = (const float*)d_in[15];
    const float* beta  = (const float*)d_in[16];
    const float* Mw    = (const float*)d_in[17];
    const float* Mb    = (const float*)d_in[18];

    float* outF   = (float*)d_out;
    float* logits = outF;                              // [N, COUT]
    float* hidden = outF + (size_t)N_*COUT_;           // [N, HID]

    lutgate_kernel<<<dim3(TLUT/128, E_), 128>>>(eW1, eb1, eW2, eb2, eW3, eb3,
                                                La, gW1, gb1, gW2, gb2);
    gemmD_tc<<<dim3(CIN_/128, 2, NS_), 256>>>(U, X);
    vs_kernel<<<1024, 256>>>(U);
    reduceP_kernel<<<K_, 256>>>(Ww);
    gemmE_tc<<<dim3(N_/256, HID_/64), 256>>>(U, Wb, hidden);
    bn_partial<<<256, 256>>>(hidden);
    bn_final<<<1, HID_>>>(gamma, beta);
    final_kernel<<<N_/8, 256>>>(hidden, Mw, Mb, logits);
}